// round 15
// baseline (speedup 1.0000x reference)
#include <cuda_runtime.h>
#include <cuda_bf16.h>
#include <cstdint>

// Banded stereo cost volume via mma.sync bf16 (3-term split precision).
// cost[j,h,x] = sum_c L[c,h,x] * R[c,h,x-j], zero when x<j.
//
// Per CTA: row h, 128-wide x-tile X0. Band of per-row GEMM D[x,y]=sum_c A[x,c]B[y,c],
// j = x - y. fp32 -> bf16 hi+lo; one K=96 pass: A'=[ah,al,ah], B'=[bh,bh,bl]
// => ah*bh + al*bh + ah*bl  (residual ~2^-16 per term).
// A: [128][96] bf16 pitch 104 (ldmatrix conflict-free). B: [NW][96] window
// y in [X0-D, X0-D+NW), zero-padded -> x<j band exact zero.
// 8 warps x 16-row strips; m16n8k16 mma; epilogue per 32-y chunk:
// accs -> buf[y][x] (pitch 132) -> diagonal gather (stride 133, conflict-free)
// -> coalesced STG of output rows j. Double-buffered, 1 barrier/chunk.

#define THREADS 256

static constexpr int PA = 104;                       // bf16 pitch (A and B rows)
static constexpr int A_OFF = 0;
static constexpr int A_BYTES = 128 * PA * 2;         // 26624
static constexpr int B_OFF = A_OFF + A_BYTES;
static constexpr int B_MAXROWS = 320;
static constexpr int B_BYTES_MAX = B_MAXROWS * PA * 2;  // 66560
static constexpr int BUF_OFF = B_OFF + B_BYTES_MAX;  // 93184 (16B aligned)
static constexpr int BUFP = 132;                     // fp32 pitch in buf
static constexpr int BUF_CHUNK = 32 * BUFP * 4;      // 16896
static constexpr int SMEM_TOTAL = BUF_OFF + 2 * BUF_CHUNK;  // 126976

__device__ __forceinline__ uint32_t smem_u32(const void* p) {
    uint32_t a;
    asm("{ .reg .u64 t; cvta.to.shared.u64 t, %1; cvt.u32.u64 %0, t; }"
        : "=r"(a) : "l"(p));
    return a;
}
__device__ __forceinline__ void ldsm_x4(uint32_t r[4], uint32_t addr) {
    asm volatile("ldmatrix.sync.aligned.m8n8.x4.shared.b16 {%0,%1,%2,%3}, [%4];"
                 : "=r"(r[0]), "=r"(r[1]), "=r"(r[2]), "=r"(r[3]) : "r"(addr));
}
__device__ __forceinline__ void ldsm_x2(uint32_t& r0, uint32_t& r1, uint32_t addr) {
    asm volatile("ldmatrix.sync.aligned.m8n8.x2.shared.b16 {%0,%1}, [%2];"
                 : "=r"(r0), "=r"(r1) : "r"(addr));
}
__device__ __forceinline__ void mma_bf16(float acc[4], const uint32_t a[4],
                                         uint32_t b0, uint32_t b1) {
    asm volatile(
        "mma.sync.aligned.m16n8k16.row.col.f32.bf16.bf16.f32 "
        "{%0,%1,%2,%3}, {%4,%5,%6,%7}, {%8,%9}, {%0,%1,%2,%3};"
        : "+f"(acc[0]), "+f"(acc[1]), "+f"(acc[2]), "+f"(acc[3])
        : "r"(a[0]), "r"(a[1]), "r"(a[2]), "r"(a[3]), "r"(b0), "r"(b1));
}

template <int H, int W, int D, int NW>
__device__ __forceinline__ void cost_volume_unit(const float* __restrict__ L,
                                                 const float* __restrict__ R,
                                                 float* __restrict__ out,
                                                 int h, int X0, char* smem)
{
    const int tid  = threadIdx.x;
    const int lane = tid & 31;
    const int wid  = tid >> 5;
    const uint32_t sb = smem_u32(smem);

    // ---- zero-fill B (covers out-of-range y rows + NW padding) ----
    {
        uint4 z = make_uint4(0u, 0u, 0u, 0u);
        uint4* p = reinterpret_cast<uint4*>(smem + B_OFF);
        constexpr int NV = NW * PA * 2 / 16;
        for (int i = tid; i < NV; i += THREADS) p[i] = z;
    }
    __syncthreads();

    // ---- stage A = L tile: row x, k = c (hi), c+32 (lo), c+64 (hi) ----
    {
        const float* Lrow = L + (size_t)h * W + X0;
        for (int i = tid; i < 32 * 128; i += THREADS) {
            int c = i >> 7, x = i & 127;
            float v = Lrow[(size_t)c * H * W + x];
            __nv_bfloat16 hi = __float2bfloat16(v);
            __nv_bfloat16 lo = __float2bfloat16(v - __bfloat162float(hi));
            __nv_bfloat16* arow =
                reinterpret_cast<__nv_bfloat16*>(smem + A_OFF) + x * PA;
            arow[c]      = hi;
            arow[c + 32] = lo;
            arow[c + 64] = hi;
        }
    }
    // ---- stage B = R window: row yl, gy = X0-D+yl; k = c (hi), c+32 (hi), c+64 (lo) ----
    {
        const int Y0 = X0 - D;
        const float* Rrow = R + (size_t)h * W;
        for (int i = tid; i < 32 * NW; i += THREADS) {
            int c = i / NW, yl = i - c * NW;
            int gy = Y0 + yl;
            if (gy < 0 || gy >= W) continue;
            float v = Rrow[(size_t)c * H * W + gy];
            __nv_bfloat16 hi = __float2bfloat16(v);
            __nv_bfloat16 lo = __float2bfloat16(v - __bfloat162float(hi));
            __nv_bfloat16* brow =
                reinterpret_cast<__nv_bfloat16*>(smem + B_OFF) + yl * PA;
            brow[c]      = hi;
            brow[c + 32] = hi;
            brow[c + 64] = lo;
        }
    }
    __syncthreads();

    // ---- load A fragments (warp strip: rows wid*16 .. wid*16+15) ----
    uint32_t af[6][4];
    {
        int row  = (lane & 7) + ((lane >> 3) & 1) * 8;
        int colo = (lane >> 4) * 8;
        uint32_t base = sb + A_OFF + (uint32_t)(((wid * 16 + row) * PA + colo) * 2);
#pragma unroll
        for (int ks = 0; ks < 6; ks++)
            ldsm_x4(af[ks], base + ks * 32);
    }
    // B ldmatrix lane offset: row n = lane&7; mat1 (lanes 8-15) at k+8.
    const uint32_t boff = (uint32_t)(((lane & 7) * PA + ((lane >> 3) & 1) * 8) * 2);

    constexpr int NCH = NW / 32;
#pragma unroll 1
    for (int g = 0; g < NCH; g++) {
        float acc[4][4];
#pragma unroll
        for (int nt = 0; nt < 4; nt++)
#pragma unroll
            for (int q = 0; q < 4; q++) acc[nt][q] = 0.0f;

#pragma unroll
        for (int nt = 0; nt < 4; nt++) {
            uint32_t bbase = sb + B_OFF +
                             (uint32_t)((g * 32 + nt * 8) * PA * 2) + boff;
#pragma unroll
            for (int ks = 0; ks < 6; ks++) {
                uint32_t b0, b1;
                ldsm_x2(b0, b1, bbase + ks * 32);
                mma_bf16(acc[nt], af[ks], b0, b1);
            }
        }

        // accs -> buf[yl][x]  (x = M row, yl = N col within chunk)
        float* buf = reinterpret_cast<float*>(smem + BUF_OFF + (g & 1) * BUF_CHUNK);
        {
            int gr = lane >> 2, tig = lane & 3;
            int xw = wid * 16 + gr;
#pragma unroll
            for (int nt = 0; nt < 4; nt++) {
                int yl = nt * 8 + 2 * tig;
                buf[yl * BUFP + xw]           = acc[nt][0];
                buf[(yl + 1) * BUFP + xw]     = acc[nt][1];
                buf[yl * BUFP + xw + 8]       = acc[nt][2];
                buf[(yl + 1) * BUFP + xw + 8] = acc[nt][3];
            }
        }
        __syncthreads();

        // diagonal gather: j = x - y_global; yl = x - (j - D + 32g)
        int jmin = D - 32 * g - 31; if (jmin < 0) jmin = 0;
        int jmax = D + 127 - 32 * g; if (jmax > D - 1) jmax = D - 1;
        for (int j = jmin + wid; j <= jmax; j += 8) {
            int base = j - D + 32 * g;
            int xlo = base < 0 ? 0 : base;
            int xhi = base + 32; if (xhi > 128) xhi = 128;
            int x = xlo + lane;
            if (x < xhi) {
                float v = buf[(x - base) * BUFP + x];   // stride 133: conflict-free
                out[(size_t)j * H * W + (size_t)h * W + X0 + x] = v;
            }
        }
        // no trailing barrier: next STS targets the other buffer, and the
        // per-iteration barrier orders gather(g) before STS(g+2).
    }
}

// Output layout: cv0 (1,192,256,512) | cv1 (1,96,128,256) | cv2 (1,48,64,128)
static constexpr size_t OUT0_ELEMS = (size_t)192 * 256 * 512;
static constexpr size_t OUT1_ELEMS = (size_t)96 * 128 * 256;

__global__ void __launch_bounds__(THREADS, 1)
cost_volume_mma_kernel(const float* __restrict__ L0, const float* __restrict__ R0,
                       const float* __restrict__ L1, const float* __restrict__ R1,
                       const float* __restrict__ L2, const float* __restrict__ R2,
                       float* __restrict__ out)
{
    extern __shared__ char smem[];
    const int b = blockIdx.x;

    if (b < 1024) {
        int h = b >> 2, X0 = (b & 3) << 7;        // scale0: 256 rows x 4 tiles
        cost_volume_unit<256, 512, 192, 320>(L0, R0, out, h, X0, smem);
    } else if (b < 1280) {
        int u = b - 1024;
        int h = u >> 1, X0 = (u & 1) << 7;        // scale1: 128 rows x 2 tiles
        cost_volume_unit<128, 256, 96, 224>(L1, R1, out + OUT0_ELEMS, h, X0, smem);
    } else {
        int h = b - 1280;                          // scale2: 64 rows x 1 tile
        cost_volume_unit<64, 128, 48, 192>(L2, R2, out + OUT0_ELEMS + OUT1_ELEMS,
                                           h, 0, smem);
    }
}

extern "C" void kernel_launch(void* const* d_in, const int* in_sizes, int n_in,
                              void* d_out, int out_size)
{
    const float* L0 = (const float*)d_in[0];
    const float* R0 = (const float*)d_in[1];
    const float* L1 = (const float*)d_in[2];
    const float* R1 = (const float*)d_in[3];
    const float* L2 = (const float*)d_in[4];
    const float* R2 = (const float*)d_in[5];
    float* out = (float*)d_out;

    static bool attr_set = false;
    if (!attr_set) {
        cudaFuncSetAttribute(cost_volume_mma_kernel,
                             cudaFuncAttributeMaxDynamicSharedMemorySize,
                             SMEM_TOTAL);
        attr_set = true;
    }

    // 1024 scale0 + 256 scale1 + 64 scale2 = 1344 units, heavy-first.
    cost_volume_mma_kernel<<<1344, THREADS, SMEM_TOTAL>>>(L0, R0, L1, R1,
                                                          L2, R2, out);
}